// round 5
// baseline (speedup 1.0000x reference)
#include <cuda_runtime.h>
#include <math.h>

// SimpleLSTM: B=64, S=1024, I=256, H=512, O=256
// W_* are [768,512]: rows 0..255 x-part, 256..767 h-part (verified, rel_err 6e-7).

#define BB 64
#define SS 1024
#define II 256
#define HH 512
#define OO 256
#define G4 2048

#define NCTA 128
#define CPC  16          // gate cols per CTA
#define HPC  4           // h cols per CTA
#define GPITCH 17        // conflict-free gate-buffer pitch

// ---------------------------------------------------------------- f32x2 ----
__device__ __forceinline__ unsigned long long pack2(float lo, float hi) {
    unsigned long long r;
    asm("mov.b64 %0, {%1, %2};" : "=l"(r) : "f"(lo), "f"(hi));
    return r;
}
__device__ __forceinline__ unsigned long long ffma2(
    unsigned long long a, unsigned long long b, unsigned long long c) {
    unsigned long long d;
    asm("fma.rn.f32x2 %0, %1, %2, %3;" : "=l"(d) : "l"(a), "l"(b), "l"(c));
    return d;
}
__device__ __forceinline__ float2 unpack2(unsigned long long v) {
    float2 f;
    asm("mov.b64 {%0, %1}, %2;" : "=f"(f.x), "=f"(f.y) : "l"(v));
    return f;
}

// fast sigmoid / tanh (NaN-safe at +-inf of the exp)
__device__ __forceinline__ float fsigmoid(float x) {
    return __fdividef(1.0f, 1.0f + __expf(-x));
}
__device__ __forceinline__ float ftanh(float x) {
    return 1.0f - 2.0f * __fdividef(1.0f, __expf(2.0f * x) + 1.0f);
}

// -------- device scratch ----------------------------------------------------
__device__ float    g_gx[(size_t)SS * BB * G4];   // [s][b][col]
__device__ float    g_hbuf[2][HH * BB];           // [k][b]
__device__ unsigned g_bar_gen;
__device__ unsigned g_bar_cnt;

// ---------------------------------------------------------------- init ----
__global__ void init_kernel() {
    int t = blockIdx.x * blockDim.x + threadIdx.x;
    int n = 2 * HH * BB;
    for (int i = t; i < n; i += gridDim.x * blockDim.x)
        ((float*)g_hbuf)[i] = 0.0f;
    if (t == 0) { g_bar_gen = 0u; g_bar_cnt = 0u; }
}

// ---------------------------------------------- input projection GEMM -----
__global__ void __launch_bounds__(256) precompute_kernel(
    const float* __restrict__ x,
    const float* __restrict__ Wf, const float* __restrict__ Wi,
    const float* __restrict__ Wc, const float* __restrict__ Wo,
    const float* __restrict__ bf, const float* __restrict__ bi,
    const float* __restrict__ bc, const float* __restrict__ bo)
{
    __shared__ float As[16][64];   // [k][s]
    __shared__ float Bs[16][64];   // [k][n]

    const int b  = blockIdx.z;
    const int s0 = blockIdx.y * 64;
    const int c0 = blockIdx.x * 64;
    const int g  = c0 >> 9;
    const int j0 = c0 & 511;

    const float* W    = (g == 0) ? Wf : (g == 1) ? Wi : (g == 2) ? Wc : Wo;
    const float* bias = (g == 0) ? bf : (g == 1) ? bi : (g == 2) ? bc : bo;

    const int t  = threadIdx.x;
    const int tx = t & 15;
    const int ty = t >> 4;

    unsigned long long acc[4][2] = {};

    const int sr = t >> 2;
    const int kq = (t & 3) * 4;

    for (int k0 = 0; k0 < II; k0 += 16) {
        float4 av = *(const float4*)&x[((size_t)b * SS + s0 + sr) * II + k0 + kq];
        As[kq + 0][sr] = av.x; As[kq + 1][sr] = av.y;
        As[kq + 2][sr] = av.z; As[kq + 3][sr] = av.w;
        #pragma unroll
        for (int i = 0; i < 4; i++) {
            int e  = t + i * 256;
            int kk = e >> 6, nn = e & 63;
            Bs[kk][nn] = W[(size_t)(k0 + kk) * HH + j0 + nn];
        }
        __syncthreads();
        #pragma unroll
        for (int k = 0; k < 16; k++) {
            float4 a = *(const float4*)&As[k][ty * 4];
            ulonglong2 w = *(const ulonglong2*)&Bs[k][tx * 4];
            unsigned long long aa;
            aa = pack2(a.x, a.x);
            acc[0][0] = ffma2(aa, w.x, acc[0][0]); acc[0][1] = ffma2(aa, w.y, acc[0][1]);
            aa = pack2(a.y, a.y);
            acc[1][0] = ffma2(aa, w.x, acc[1][0]); acc[1][1] = ffma2(aa, w.y, acc[1][1]);
            aa = pack2(a.z, a.z);
            acc[2][0] = ffma2(aa, w.x, acc[2][0]); acc[2][1] = ffma2(aa, w.y, acc[2][1]);
            aa = pack2(a.w, a.w);
            acc[3][0] = ffma2(aa, w.x, acc[3][0]); acc[3][1] = ffma2(aa, w.y, acc[3][1]);
        }
        __syncthreads();
    }

    float4 bv = *(const float4*)&bias[j0 + tx * 4];
    #pragma unroll
    for (int mi = 0; mi < 4; mi++) {
        int s = s0 + ty * 4 + mi;
        float2 q0 = unpack2(acc[mi][0]);
        float2 q1 = unpack2(acc[mi][1]);
        float4 v;
        v.x = q0.x + bv.x; v.y = q0.y + bv.y;
        v.z = q1.x + bv.z; v.w = q1.y + bv.w;
        *(float4*)&g_gx[((size_t)s * BB + b) * G4 + c0 + tx * 4] = v;
    }
}

// ----------------------------------------- persistent recurrent kernel ----
// CTA owns gate cols {g*512 + cta*4 + l}. 256 threads, 2 k-split groups of 128.
// h staged in 4 chunks of 64 k-rows, register-double-buffered under the GEMM.
#define SMEM_FLOATS (HH * BB + HH * CPC + 2 * BB * GPITCH)

__global__ void __launch_bounds__(256, 1) step_kernel(
    const float* __restrict__ Wf, const float* __restrict__ Wi,
    const float* __restrict__ Wc, const float* __restrict__ Wo)
{
    extern __shared__ float sm[];
    float* h_s  = sm;                        // [k][b]   512x64
    float* W_s  = sm + HH * BB;              // [k][cc]  512x16
    float* gbuf = sm + HH * BB + HH * CPC;   // 2 slabs of [b][GPITCH]

    const int cta = blockIdx.x;
    const int t   = threadIdx.x;

    // Load W_h slice (rows 256..767), once.
    for (int e = t; e < HH * CPC; e += 256) {
        int k = e >> 4, cc = e & 15;
        int g = cc >> 2, l = cc & 3;
        const float* W = (g == 0) ? Wf : (g == 1) ? Wi : (g == 2) ? Wc : Wo;
        W_s[k * CPC + cc] = W[(size_t)(II + k) * HH + cta * HPC + l];
    }
    __syncthreads();

    const int kg = t >> 7;           // k-split group 0/1
    const int t2 = t & 127;
    const int ty = t2 >> 6;          // col half: cc base = ty*8
    const int b  = t2 & 63;
    const int c0 = ty * 8;
    const int k0 = kg * (HH / 2);
    float* gslab = gbuf + kg * (BB * GPITCH);

    const int ub = t & 63, ul = t >> 6;   // update-phase cell (b, l)
    float c_reg = 0.0f;

    // Seeds for step 0 (kg==0 threads only).
    float4 ga = {0,0,0,0}, gb = {0,0,0,0};
    if (kg == 0) {
        const float* gx = &g_gx[(size_t)b * G4 + cta * HPC];
        ga = *(const float4*)&gx[(ty * 2    ) * HH];
        gb = *(const float4*)&gx[(ty * 2 + 1) * HH];
    }

    for (int s = 0; s < SS; s++) {
        const int par = s & 1;

        const float4* hsrc = (const float4*)&g_hbuf[par][k0 * BB];
        float4*       hdst = (float4*)&h_s[k0 * BB];

        // Load chunk 0 of this group's half into registers (L2 path).
        float4 buf[8];
        #pragma unroll
        for (int i = 0; i < 8; i++)
            buf[i] = __ldcg(hsrc + i * 128 + t2);

        // Accumulators: group 0 seeds from prefetched Gx, group 1 zero;
        // then prefetch next step's seeds (independent of h).
        unsigned long long a0, a1, a2, a3;
        if (kg == 0) {
            a0 = pack2(ga.x, ga.y); a1 = pack2(ga.z, ga.w);
            a2 = pack2(gb.x, gb.y); a3 = pack2(gb.z, gb.w);
            if (s + 1 < SS) {
                const float* gx = &g_gx[(size_t)(s + 1) * BB * G4
                                        + (size_t)b * G4 + cta * HPC];
                ga = *(const float4*)&gx[(ty * 2    ) * HH];
                gb = *(const float4*)&gx[(ty * 2 + 1) * HH];
            }
        } else {
            a0 = a1 = a2 = a3 = 0ull;
        }

        // 4 chunks of 64 k-rows: store regs->smem, start next chunk's loads,
        // sync, GEMM the stored chunk. Loads hide under the previous GEMM.
        #pragma unroll
        for (int c = 0; c < 4; c++) {
            #pragma unroll
            for (int i = 0; i < 8; i++)
                hdst[c * 1024 + i * 128 + t2] = buf[i];
            if (c < 3) {
                #pragma unroll
                for (int i = 0; i < 8; i++)
                    buf[i] = __ldcg(hsrc + (c + 1) * 1024 + i * 128 + t2);
            }
            __syncthreads();

            const int kc = k0 + c * 64;
            #pragma unroll 8
            for (int k = kc; k < kc + 64; k++) {
                float h = h_s[k * BB + b];
                unsigned long long hh = pack2(h, h);
                ulonglong2 wA = *(const ulonglong2*)&W_s[k * CPC + c0];
                ulonglong2 wB = *(const ulonglong2*)&W_s[k * CPC + c0 + 4];
                a0 = ffma2(hh, wA.x, a0); a1 = ffma2(hh, wA.y, a1);
                a2 = ffma2(hh, wB.x, a2); a3 = ffma2(hh, wB.y, a3);
            }
        }

        // Spill partials (conflict-free pitch).
        {
            float2 p;
            float* row = &gslab[b * GPITCH + c0];
            p = unpack2(a0); row[0] = p.x; row[1] = p.y;
            p = unpack2(a1); row[2] = p.x; row[3] = p.y;
            p = unpack2(a2); row[4] = p.x; row[5] = p.y;
            p = unpack2(a3); row[6] = p.x; row[7] = p.y;
        }
        __syncthreads();

        // Gates + cell update (fast activations).
        {
            const float* r0 = &gbuf[ub * GPITCH];
            const float* r1 = &gbuf[BB * GPITCH + ub * GPITCH];
            float gf = r0[0 * HPC + ul] + r1[0 * HPC + ul];
            float gi = r0[1 * HPC + ul] + r1[1 * HPC + ul];
            float gu = r0[2 * HPC + ul] + r1[2 * HPC + ul];
            float go = r0[3 * HPC + ul] + r1[3 * HPC + ul];
            float f = fsigmoid(gf);
            float i = fsigmoid(gi);
            float u = ftanh(gu);
            float o = fsigmoid(go);
            c_reg = f * c_reg + i * u;
            float hnew = o * ftanh(c_reg);
            g_hbuf[1 - par][(cta * HPC + ul) * BB + ub] = hnew;
        }

        // ---- chip-wide barrier: verbatim from R3 (proven to pass) ---------
        __threadfence();
        __syncthreads();
        if (t == 0) {
            unsigned arrived = atomicAdd(&g_bar_cnt, 1u) + 1u;
            if (arrived == (unsigned)NCTA * (unsigned)(s + 1)) {
                __threadfence();
                atomicAdd(&g_bar_gen, 1u);          // release
            } else {
                unsigned gen;
                do {
                    asm volatile("ld.acquire.gpu.u32 %0, [%1];"
                                 : "=r"(gen) : "l"(&g_bar_gen) : "memory");
                } while (gen <= (unsigned)s);
            }
            __threadfence();   // acquire fence: order flag -> subsequent h reads
        }
        __syncthreads();
    }
}

// -------------------------------------------------------- output head -----
__global__ void __launch_bounds__(256) out_kernel(
    const float* __restrict__ Wout, const float* __restrict__ bout,
    float* __restrict__ out)
{
    __shared__ float hsh[HH];
    const int b = blockIdx.x;
    const int j = threadIdx.x;
    for (int k = j; k < HH; k += 256)
        hsh[k] = g_hbuf[0][k * BB + b];
    __syncthreads();

    float a0 = 0.f, a1 = 0.f, a2 = 0.f, a3 = 0.f;
    #pragma unroll 4
    for (int k = 0; k < HH; k += 4) {
        a0 += hsh[k + 0] * Wout[(size_t)(k + 0) * OO + j];
        a1 += hsh[k + 1] * Wout[(size_t)(k + 1) * OO + j];
        a2 += hsh[k + 2] * Wout[(size_t)(k + 2) * OO + j];
        a3 += hsh[k + 3] * Wout[(size_t)(k + 3) * OO + j];
    }
    out[(size_t)b * OO + j] = a0 + a1 + a2 + a3 + bout[j];
}

// ------------------------------------------------------------ launcher ----
extern "C" void kernel_launch(void* const* d_in, const int* in_sizes, int n_in,
                              void* d_out, int out_size)
{
    (void)in_sizes; (void)n_in; (void)out_size;
    const float* x    = (const float*)d_in[0];
    const float* Wf   = (const float*)d_in[1];
    const float* bf   = (const float*)d_in[2];
    const float* Wi   = (const float*)d_in[3];
    const float* bi   = (const float*)d_in[4];
    const float* Wc   = (const float*)d_in[5];
    const float* bc   = (const float*)d_in[6];
    const float* Wo   = (const float*)d_in[7];
    const float* bo   = (const float*)d_in[8];
    const float* Wout = (const float*)d_in[9];
    const float* bout = (const float*)d_in[10];
    float* out = (float*)d_out;

    cudaFuncSetAttribute(step_kernel,
                         cudaFuncAttributeMaxDynamicSharedMemorySize,
                         SMEM_FLOATS * (int)sizeof(float));

    init_kernel<<<32, 256>>>();
    precompute_kernel<<<dim3(G4 / 64, SS / 64, BB), 256>>>(
        x, Wf, Wi, Wc, Wo, bf, bi, bc, bo);
    step_kernel<<<NCTA, 256, SMEM_FLOATS * (int)sizeof(float)>>>(Wf, Wi, Wc, Wo);
    out_kernel<<<BB, 256>>>(Wout, bout, out);
}

// round 6
// speedup vs baseline: 1.0799x; 1.0799x over previous
#include <cuda_runtime.h>
#include <math.h>

// SimpleLSTM: B=64, S=1024, I=256, H=512, O=256
// W_* are [768,512]: rows 0..255 x-part, 256..767 h-part.

#define BB 64
#define SS 1024
#define II 256
#define HH 512
#define OO 256
#define G4 2048

#define NCTA 128
#define CPC  16          // gate cols per CTA
#define HPC  4           // h cols per CTA
#define GPITCH 17        // conflict-free gate-buffer pitch
#define NKG  4           // k-split groups (64 threads each, 128 k-rows each)
#define GSLAB (BB * GPITCH)

// barrier tree: 16 groups of 8 CTAs
#define BAR_GRPS 16
#define BAR_GRP_SZ 8
#define BAR_PAD 32       // 128B stride between group counters

// ---------------------------------------------------------------- f32x2 ----
__device__ __forceinline__ unsigned long long pack2(float lo, float hi) {
    unsigned long long r;
    asm("mov.b64 %0, {%1, %2};" : "=l"(r) : "f"(lo), "f"(hi));
    return r;
}
__device__ __forceinline__ unsigned long long ffma2(
    unsigned long long a, unsigned long long b, unsigned long long c) {
    unsigned long long d;
    asm("fma.rn.f32x2 %0, %1, %2, %3;" : "=l"(d) : "l"(a), "l"(b), "l"(c));
    return d;
}
__device__ __forceinline__ float2 unpack2(unsigned long long v) {
    float2 f;
    asm("mov.b64 {%0, %1}, %2;" : "=f"(f.x), "=f"(f.y) : "l"(v));
    return f;
}

// fast sigmoid / tanh (NaN-safe at +-inf of the exp)
__device__ __forceinline__ float fsigmoid(float x) {
    return __fdividef(1.0f, 1.0f + __expf(-x));
}
__device__ __forceinline__ float ftanh(float x) {
    return 1.0f - 2.0f * __fdividef(1.0f, __expf(2.0f * x) + 1.0f);
}

// -------- device scratch ----------------------------------------------------
__device__ float    g_gx[(size_t)SS * BB * G4];   // [s][b][col]
__device__ float    g_hbuf[2][HH * BB];           // [k][b]
__device__ unsigned g_grp_cnt[BAR_GRPS * BAR_PAD];
__device__ unsigned g_root_cnt;
__device__ unsigned g_bar_gen;

// ---------------------------------------------------------------- init ----
__global__ void init_kernel() {
    int t = blockIdx.x * blockDim.x + threadIdx.x;
    int n = 2 * HH * BB;
    for (int i = t; i < n; i += gridDim.x * blockDim.x)
        ((float*)g_hbuf)[i] = 0.0f;
    if (t < BAR_GRPS * BAR_PAD) g_grp_cnt[t] = 0u;
    if (t == 0) { g_root_cnt = 0u; g_bar_gen = 0u; }
}

// ---------------------------------------------- input projection GEMM -----
__global__ void __launch_bounds__(256) precompute_kernel(
    const float* __restrict__ x,
    const float* __restrict__ Wf, const float* __restrict__ Wi,
    const float* __restrict__ Wc, const float* __restrict__ Wo,
    const float* __restrict__ bf, const float* __restrict__ bi,
    const float* __restrict__ bc, const float* __restrict__ bo)
{
    __shared__ float As[16][64];   // [k][s]
    __shared__ float Bs[16][64];   // [k][n]

    const int b  = blockIdx.z;
    const int s0 = blockIdx.y * 64;
    const int c0 = blockIdx.x * 64;
    const int g  = c0 >> 9;
    const int j0 = c0 & 511;

    const float* W    = (g == 0) ? Wf : (g == 1) ? Wi : (g == 2) ? Wc : Wo;
    const float* bias = (g == 0) ? bf : (g == 1) ? bi : (g == 2) ? bc : bo;

    const int t  = threadIdx.x;
    const int tx = t & 15;
    const int ty = t >> 4;

    unsigned long long acc[4][2] = {};

    const int sr = t >> 2;
    const int kq = (t & 3) * 4;

    for (int k0 = 0; k0 < II; k0 += 16) {
        float4 av = *(const float4*)&x[((size_t)b * SS + s0 + sr) * II + k0 + kq];
        As[kq + 0][sr] = av.x; As[kq + 1][sr] = av.y;
        As[kq + 2][sr] = av.z; As[kq + 3][sr] = av.w;
        #pragma unroll
        for (int i = 0; i < 4; i++) {
            int e  = t + i * 256;
            int kk = e >> 6, nn = e & 63;
            Bs[kk][nn] = W[(size_t)(k0 + kk) * HH + j0 + nn];
        }
        __syncthreads();
        #pragma unroll
        for (int k = 0; k < 16; k++) {
            float4 a = *(const float4*)&As[k][ty * 4];
            ulonglong2 w = *(const ulonglong2*)&Bs[k][tx * 4];
            unsigned long long aa;
            aa = pack2(a.x, a.x);
            acc[0][0] = ffma2(aa, w.x, acc[0][0]); acc[0][1] = ffma2(aa, w.y, acc[0][1]);
            aa = pack2(a.y, a.y);
            acc[1][0] = ffma2(aa, w.x, acc[1][0]); acc[1][1] = ffma2(aa, w.y, acc[1][1]);
            aa = pack2(a.z, a.z);
            acc[2][0] = ffma2(aa, w.x, acc[2][0]); acc[2][1] = ffma2(aa, w.y, acc[2][1]);
            aa = pack2(a.w, a.w);
            acc[3][0] = ffma2(aa, w.x, acc[3][0]); acc[3][1] = ffma2(aa, w.y, acc[3][1]);
        }
        __syncthreads();
    }

    float4 bv = *(const float4*)&bias[j0 + tx * 4];
    #pragma unroll
    for (int mi = 0; mi < 4; mi++) {
        int s = s0 + ty * 4 + mi;
        float2 q0 = unpack2(acc[mi][0]);
        float2 q1 = unpack2(acc[mi][1]);
        float4 v;
        v.x = q0.x + bv.x; v.y = q0.y + bv.y;
        v.z = q1.x + bv.z; v.w = q1.y + bv.w;
        *(float4*)&g_gx[((size_t)s * BB + b) * G4 + c0 + tx * 4] = v;
    }
}

// ----------------------------------------- persistent recurrent kernel ----
// CTA owns gate cols {g*512 + cta*4 + l : g<4, l<4}. 256 threads =
// 4 k-groups of 64; each group: 128 k-rows, thread tile 2 batches x 8 cols.
#define SMEM_FLOATS (HH * BB + HH * CPC + NKG * GSLAB)

__global__ void __launch_bounds__(256, 1) step_kernel(
    const float* __restrict__ Wf, const float* __restrict__ Wi,
    const float* __restrict__ Wc, const float* __restrict__ Wo)
{
    extern __shared__ float sm[];
    float* h_s  = sm;                        // [k][b]   512x64
    float* W_s  = sm + HH * BB;              // [k][cc]  512x16
    float* gbuf = sm + HH * BB + HH * CPC;   // NKG slabs of [b][GPITCH]

    const int cta = blockIdx.x;
    const int t   = threadIdx.x;

    // Load W_h slice (rows 256..767), once.
    for (int e = t; e < HH * CPC; e += 256) {
        int k = e >> 4, cc = e & 15;
        int g = cc >> 2, l = cc & 3;
        const float* W = (g == 0) ? Wf : (g == 1) ? Wi : (g == 2) ? Wc : Wo;
        W_s[k * CPC + cc] = W[(size_t)(II + k) * HH + cta * HPC + l];
    }
    __syncthreads();

    const int kg = t >> 6;                 // k-group 0..3 (warp-pair aligned)
    const int t6 = t & 63;
    const int ty = t6 >> 5;                // col half: cc base = ty*8
    const int b0 = (t6 & 31) * 2;          // this thread's batch pair
    const int c0 = ty * 8;
    const int k0 = kg * (HH / NKG);        // 128 k-rows per group
    float* gslab = gbuf + kg * GSLAB;

    const int ub = t & 63, ul = t >> 6;    // update-phase cell (b, l); ul<4 ok
    float c_reg = 0.0f;

    // Seeds for step 0 (kg==0 threads only): 2 batches x 8 cols.
    float4 s00 = {0,0,0,0}, s01 = {0,0,0,0}, s10 = {0,0,0,0}, s11 = {0,0,0,0};
    if (kg == 0) {
        const float* gx = &g_gx[(size_t)b0 * G4 + cta * HPC];
        s00 = *(const float4*)&gx[(ty * 2    ) * HH];
        s01 = *(const float4*)&gx[(ty * 2 + 1) * HH];
        s10 = *(const float4*)&gx[G4 + (ty * 2    ) * HH];
        s11 = *(const float4*)&gx[G4 + (ty * 2 + 1) * HH];
    }

    for (int s = 0; s < SS; s++) {
        const int par = s & 1;

        const float4* hsrc = (const float4*)&g_hbuf[par][k0 * BB];
        float4*       hdst = (float4*)&h_s[k0 * BB];

        // Chunk 0 of this group's strip (32 k-rows = 512 f4 / 64 thr = 8 each).
        float4 buf[8];
        #pragma unroll
        for (int i = 0; i < 8; i++)
            buf[i] = __ldcg(hsrc + i * 64 + t6);

        // Accumulators (2b x 8c as 8 f32x2); kg==0 seeds from Gx.
        unsigned long long a0, a1, a2, a3, a4, a5, a6, a7;
        if (kg == 0) {
            a0 = pack2(s00.x, s00.y); a1 = pack2(s00.z, s00.w);
            a2 = pack2(s01.x, s01.y); a3 = pack2(s01.z, s01.w);
            a4 = pack2(s10.x, s10.y); a5 = pack2(s10.z, s10.w);
            a6 = pack2(s11.x, s11.y); a7 = pack2(s11.z, s11.w);
            if (s + 1 < SS) {
                const float* gx = &g_gx[(size_t)(s + 1) * BB * G4
                                        + (size_t)b0 * G4 + cta * HPC];
                s00 = *(const float4*)&gx[(ty * 2    ) * HH];
                s01 = *(const float4*)&gx[(ty * 2 + 1) * HH];
                s10 = *(const float4*)&gx[G4 + (ty * 2    ) * HH];
                s11 = *(const float4*)&gx[G4 + (ty * 2 + 1) * HH];
            }
        } else {
            a0 = a1 = a2 = a3 = a4 = a5 = a6 = a7 = 0ull;
        }

        // 4 chunks of 32 k-rows, register-double-buffered.
        #pragma unroll
        for (int c = 0; c < 4; c++) {
            #pragma unroll
            for (int i = 0; i < 8; i++)
                hdst[c * 512 + i * 64 + t6] = buf[i];
            if (c < 3) {
                #pragma unroll
                for (int i = 0; i < 8; i++)
                    buf[i] = __ldcg(hsrc + (c + 1) * 512 + i * 64 + t6);
            }
            __syncthreads();

            const int kc = k0 + c * 32;
            #pragma unroll 8
            for (int k = kc; k < kc + 32; k++) {
                float2 hv = *(const float2*)&h_s[k * BB + b0];
                unsigned long long h0 = pack2(hv.x, hv.x);
                unsigned long long h1 = pack2(hv.y, hv.y);
                ulonglong2 wA = *(const ulonglong2*)&W_s[k * CPC + c0];
                ulonglong2 wB = *(const ulonglong2*)&W_s[k * CPC + c0 + 4];
                a0 = ffma2(h0, wA.x, a0); a1 = ffma2(h0, wA.y, a1);
                a2 = ffma2(h0, wB.x, a2); a3 = ffma2(h0, wB.y, a3);
                a4 = ffma2(h1, wA.x, a4); a5 = ffma2(h1, wA.y, a5);
                a6 = ffma2(h1, wB.x, a6); a7 = ffma2(h1, wB.y, a7);
            }
        }

        // Spill partials.
        {
            float2 p;
            float* r0 = &gslab[b0 * GPITCH + c0];
            float* r1 = &gslab[(b0 + 1) * GPITCH + c0];
            p = unpack2(a0); r0[0] = p.x; r0[1] = p.y;
            p = unpack2(a1); r0[2] = p.x; r0[3] = p.y;
            p = unpack2(a2); r0[4] = p.x; r0[5] = p.y;
            p = unpack2(a3); r0[6] = p.x; r0[7] = p.y;
            p = unpack2(a4); r1[0] = p.x; r1[1] = p.y;
            p = unpack2(a5); r1[2] = p.x; r1[3] = p.y;
            p = unpack2(a6); r1[4] = p.x; r1[5] = p.y;
            p = unpack2(a7); r1[6] = p.x; r1[7] = p.y;
        }
        __syncthreads();

        // Gates + cell update: sum the NKG k-partials.
        {
            float gf = 0.f, gi = 0.f, gu = 0.f, go = 0.f;
            #pragma unroll
            for (int q = 0; q < NKG; q++) {
                const float* r = &gbuf[q * GSLAB + ub * GPITCH];
                gf += r[0 * HPC + ul];
                gi += r[1 * HPC + ul];
                gu += r[2 * HPC + ul];
                go += r[3 * HPC + ul];
            }
            float f = fsigmoid(gf);
            float i = fsigmoid(gi);
            float u = ftanh(gu);
            float o = fsigmoid(go);
            c_reg = f * c_reg + i * u;
            float hnew = o * ftanh(c_reg);
            g_hbuf[1 - par][(cta * HPC + ul) * BB + ub] = hnew;
        }

        // ---- chip-wide barrier: 2-level tree, R3 fence mechanics ----------
        __threadfence();
        __syncthreads();
        if (t == 0) {
            const int grp = cta >> 3;      // 16 groups of 8
            unsigned a = atomicAdd(&g_grp_cnt[grp * BAR_PAD], 1u) + 1u;
            if (a == (unsigned)BAR_GRP_SZ * (unsigned)(s + 1)) {
                unsigned r = atomicAdd(&g_root_cnt, 1u) + 1u;
                if (r == (unsigned)BAR_GRPS * (unsigned)(s + 1)) {
                    __threadfence();
                    atomicAdd(&g_bar_gen, 1u);      // release
                } else {
                    unsigned gen;
                    do {
                        asm volatile("ld.acquire.gpu.u32 %0, [%1];"
                                     : "=r"(gen) : "l"(&g_bar_gen) : "memory");
                    } while (gen <= (unsigned)s);
                }
            } else {
                unsigned gen;
                do {
                    asm volatile("ld.acquire.gpu.u32 %0, [%1];"
                                 : "=r"(gen) : "l"(&g_bar_gen) : "memory");
                } while (gen <= (unsigned)s);
            }
            __threadfence();
        }
        __syncthreads();
    }
}

// -------------------------------------------------------- output head -----
__global__ void __launch_bounds__(256) out_kernel(
    const float* __restrict__ Wout, const float* __restrict__ bout,
    float* __restrict__ out)
{
    __shared__ float hsh[HH];
    const int b = blockIdx.x;
    const int j = threadIdx.x;
    for (int k = j; k < HH; k += 256)
        hsh[k] = g_hbuf[0][k * BB + b];
    __syncthreads();

    float a0 = 0.f, a1 = 0.f, a2 = 0.f, a3 = 0.f;
    #pragma unroll 4
    for (int k = 0; k < HH; k += 4) {
        a0 += hsh[k + 0] * Wout[(size_t)(k + 0) * OO + j];
        a1 += hsh[k + 1] * Wout[(size_t)(k + 1) * OO + j];
        a2 += hsh[k + 2] * Wout[(size_t)(k + 2) * OO + j];
        a3 += hsh[k + 3] * Wout[(size_t)(k + 3) * OO + j];
    }
    out[(size_t)b * OO + j] = a0 + a1 + a2 + a3 + bout[j];
}

// ------------------------------------------------------------ launcher ----
extern "C" void kernel_launch(void* const* d_in, const int* in_sizes, int n_in,
                              void* d_out, int out_size)
{
    (void)in_sizes; (void)n_in; (void)out_size;
    const float* x    = (const float*)d_in[0];
    const float* Wf   = (const float*)d_in[1];
    const float* bf   = (const float*)d_in[2];
    const float* Wi   = (const float*)d_in[3];
    const float* bi   = (const float*)d_in[4];
    const float* Wc   = (const float*)d_in[5];
    const float* bc   = (const float*)d_in[6];
    const float* Wo   = (const float*)d_in[7];
    const float* bo   = (const float*)d_in[8];
    const float* Wout = (const float*)d_in[9];
    const float* bout = (const float*)d_in[10];
    float* out = (float*)d_out;

    cudaFuncSetAttribute(step_kernel,
                         cudaFuncAttributeMaxDynamicSharedMemorySize,
                         SMEM_FLOATS * (int)sizeof(float));

    init_kernel<<<32, 256>>>();
    precompute_kernel<<<dim3(G4 / 64, SS / 64, BB), 256>>>(
        x, Wf, Wi, Wc, Wo, bf, bi, bc, bo);
    step_kernel<<<NCTA, 256, SMEM_FLOATS * (int)sizeof(float)>>>(Wf, Wi, Wc, Wo);
    out_kernel<<<BB, 256>>>(Wout, bout, out);
}